// round 8
// baseline (speedup 1.0000x reference)
#include <cuda_runtime.h>
#include <math.h>

#define N_TOT   4096
#define N_UP    2048
#define HIDDEN  32
#define BOX     10.0f
#define TBL     4096
#define SMAX    25.0f        // r_cut^2 = 5^2
#define CHUNK   64
#define THREADS 256          // main kernel CTA size (rows per CTA)
#define BTHREADS 256         // build kernel CTA size
#define INIT_CTAS 16

#define MAGIC     12582912.0f        // 1.5 * 2^23
#define BASEBITS  0x4B400000u        // float bits of MAGIC
#define CAPBITS   (BASEBITS + (TBL - 1))

typedef unsigned long long u64;

// ---- packed f32x2 helpers (sm_103a; ptxas never emits these from C++) ----
__device__ __forceinline__ u64 pk2(float lo, float hi) {
    u64 r; asm("mov.b64 %0,{%1,%2};" : "=l"(r) : "f"(lo), "f"(hi)); return r;
}
__device__ __forceinline__ void upk2u(u64 v, unsigned& lo, unsigned& hi) {
    asm("mov.b64 {%0,%1},%2;" : "=r"(lo), "=r"(hi) : "l"(v));
}
__device__ __forceinline__ void upk2(u64 v, float& lo, float& hi) {
    asm("mov.b64 {%0,%1},%2;" : "=f"(lo), "=f"(hi) : "l"(v));
}
__device__ __forceinline__ u64 add2(u64 a, u64 b) {
    u64 r; asm("add.rn.f32x2 %0,%1,%2;" : "=l"(r) : "l"(a), "l"(b)); return r;
}
__device__ __forceinline__ u64 mul2(u64 a, u64 b) {
    u64 r; asm("mul.rn.f32x2 %0,%1,%2;" : "=l"(r) : "l"(a), "l"(b)); return r;
}
__device__ __forceinline__ u64 fma2(u64 a, u64 b, u64 c) {
    u64 r; asm("fma.rn.f32x2 %0,%1,%2,%3;" : "=l"(r) : "l"(a), "l"(b), "l"(c)); return r;
}

// Precomputed f(s) tables (values pre-divided by coord scale cs).
// Nearest-neighbor lookup: plain float entries. [0]=same, [1]=diff.
__device__ __align__(16) float g_tab[2][TBL];

// ---------------------------------------------------------------------------
__device__ __forceinline__ float decay_of_s(float s) {
    float r  = sqrtf(s + 1e-15f);
    float xn = fminf(r * (1.0f / 5.0f), 1.0f - 1e-5f);
    float u  = 1.0f - xn * xn;
    return expf(1.0f - 1.0f / u);
}
__device__ __forceinline__ float unit_contrib(float decay, float w1, float b1, float wo) {
    float z = fmaf(decay, w1, b1);
    float h = z / (1.0f + expf(-z));
    return h * wo;
}

// Fused: build tables (warp per entry, lane per hidden unit) + out=rs init.
__global__ void __launch_bounds__(BTHREADS)
build_and_init(const float* __restrict__ rs, float* __restrict__ out,
               const float* __restrict__ sw1, const float* __restrict__ sb1,
               const float* __restrict__ swo, const float* __restrict__ sbo,
               const float* __restrict__ dw1, const float* __restrict__ db1,
               const float* __restrict__ dwo, const float* __restrict__ dbo) {
    const int bid = blockIdx.x;
    const int tid = threadIdx.x;

    if (bid < INIT_CTAS) {
        for (int i = bid * BTHREADS + tid; i < N_TOT * 3; i += INIT_CTAS * BTHREADS)
            out[i] = rs[i];
        return;
    }

    const int wglob = (bid - INIT_CTAS) * (BTHREADS / 32) + (tid >> 5);
    if (wglob >= 2 * TBL) return;
    const int net  = wglob / TBL;
    const int k    = wglob % TBL;
    const int lane = tid & 31;

    const float w1 = net ? dw1[lane] : sw1[lane];
    const float b1 = net ? db1[lane] : sb1[lane];
    const float wo = net ? dwo[lane] : swo[lane];
    const float bo = net ? dbo[0]    : sbo[0];

    const float h = SMAX / (float)(TBL - 1);
    const float d0 = decay_of_s((float)k * h);

    float a0 = unit_contrib(d0, w1, b1, wo);
    #pragma unroll
    for (int off = 16; off > 0; off >>= 1)
        a0 += __shfl_xor_sync(0xFFFFFFFFu, a0, off);
    if (lane == 0) {
        const float cs = sqrtf((float)(TBL - 1) / SMAX);   // coord scale
        g_tab[net][k] = (a0 + bo) * d0 / cs;
    }
}

// ---------------------------------------------------------------------------
// Main pairwise kernel: grid (16 x 64) = 1024 CTAs, 256 threads.
// Coordinates pre-scaled so t = |d'|^2 is the table coordinate (nearest).
// TWO independent packed streams per thread (pairs c and c+CHUNK/4) for ILP.
// ---------------------------------------------------------------------------
__global__ void __launch_bounds__(THREADS)
backflow_kernel(const float* __restrict__ rs, float* __restrict__ out) {
    __shared__ __align__(16) float s_tab[TBL];             // 16 KB
    // per j-pair: (x0,x1,y0,y1) as ulonglong2, (z0,z1) as u64
    __shared__ __align__(16) ulonglong2 sjxy[CHUNK / 2];
    __shared__ __align__(16) u64        sjz [CHUNK / 2];

    const int tid    = threadIdx.x;
    const int rowBlk = blockIdx.x;       // 0..15 (256 rows each)
    const int jBlk   = blockIdx.y;       // 0..63 (64 cols each)
    const int i      = rowBlk * THREADS + tid;
    const int j0     = jBlk * CHUNK;

    const int net = ((rowBlk < 8) == (jBlk < 32)) ? 0 : 1;

    const float cs   = sqrtf((float)(TBL - 1) / SMAX);   // coord scale
    const float BOXS = BOX * cs;

    // stage table (16 KB): 1024 float4 over 256 threads
    {
        const float4* src = (const float4*)g_tab[net];
        float4*       dst = (float4*)s_tab;
        #pragma unroll
        for (int t = tid; t < TBL / 4; t += THREADS) dst[t] = src[t];
    }
    if (tid < CHUNK) {
        int j = j0 + tid;
        int c = tid >> 1, l = tid & 1;
        float* fxy = (float*)sjxy;
        float* fz  = (float*)sjz;
        fxy[4 * c + l]     = -cs * rs[3 * j + 0];
        fxy[4 * c + 2 + l] = -cs * rs[3 * j + 1];
        fz [2 * c + l]     = -cs * rs[3 * j + 2];
    }
    __syncthreads();

    const float xi = cs * rs[3 * i + 0];
    const float yi = cs * rs[3 * i + 1];
    const float zi = cs * rs[3 * i + 2];
    const u64 xi2 = pk2(xi, xi);
    const u64 yi2 = pk2(yi, yi);
    const u64 zi2 = pk2(zi, zi);

    const u64 c_invb = pk2(1.0f / BOXS, 1.0f / BOXS);
    const u64 c_mag  = pk2(MAGIC, MAGIC);
    const u64 c_nmag = pk2(-MAGIC, -MAGIC);
    const u64 c_nb   = pk2(-BOXS, -BOXS);

    // two independent accumulator streams
    u64 axA = 0, ayA = 0, azA = 0;
    u64 axB = 0, ayB = 0, azB = 0;

    #pragma unroll 4
    for (int c = 0; c < CHUNK / 4; c++) {
        const int cA = c;
        const int cB = c + CHUNK / 4;

        const ulonglong2 pA = sjxy[cA];    // broadcast LDS.128
        const u64        zA = sjz [cA];    // broadcast LDS.64
        const ulonglong2 pB = sjxy[cB];
        const u64        zB = sjz [cB];

        // ---- stream A ----
        u64 dxA = add2(xi2, pA.x);
        u64 dyA = add2(yi2, pA.y);
        u64 dzA = add2(zi2, zA);
        u64 mxA = fma2(dxA, c_invb, c_mag);
        u64 myA = fma2(dyA, c_invb, c_mag);
        u64 mzA = fma2(dzA, c_invb, c_mag);
        dxA = fma2(add2(mxA, c_nmag), c_nb, dxA);
        dyA = fma2(add2(myA, c_nmag), c_nb, dyA);
        dzA = fma2(add2(mzA, c_nmag), c_nb, dzA);
        u64 tA = fma2(dxA, dxA, fma2(dyA, dyA, mul2(dzA, dzA)));
        u64 mA = add2(tA, c_mag);

        // ---- stream B ----
        u64 dxB = add2(xi2, pB.x);
        u64 dyB = add2(yi2, pB.y);
        u64 dzB = add2(zi2, zB);
        u64 mxB = fma2(dxB, c_invb, c_mag);
        u64 myB = fma2(dyB, c_invb, c_mag);
        u64 mzB = fma2(dzB, c_invb, c_mag);
        dxB = fma2(add2(mxB, c_nmag), c_nb, dxB);
        dyB = fma2(add2(myB, c_nmag), c_nb, dyB);
        dzB = fma2(add2(mzB, c_nmag), c_nb, dzB);
        u64 tB = fma2(dxB, dxB, fma2(dyB, dyB, mul2(dzB, dzB)));
        u64 mB = add2(tB, c_mag);

        unsigned kA0, kA1, kB0, kB1;
        upk2u(mA, kA0, kA1);
        upk2u(mB, kB0, kB1);
        kA0 = min(kA0, CAPBITS); kA1 = min(kA1, CAPBITS);
        kB0 = min(kB0, CAPBITS); kB1 = min(kB1, CAPBITS);

        float fA0 = s_tab[kA0 - BASEBITS];
        float fA1 = s_tab[kA1 - BASEBITS];
        float fB0 = s_tab[kB0 - BASEBITS];
        float fB1 = s_tab[kB1 - BASEBITS];

        const u64 fA = pk2(fA0, fA1);
        const u64 fB = pk2(fB0, fB1);
        axA = fma2(fA, dxA, axA);
        ayA = fma2(fA, dyA, ayA);
        azA = fma2(fA, dzA, azA);
        axB = fma2(fB, dxB, axB);
        ayB = fma2(fB, dyB, ayB);
        azB = fma2(fB, dzB, azB);
    }

    const u64 ax2 = add2(axA, axB);
    const u64 ay2 = add2(ayA, ayB);
    const u64 az2 = add2(azA, azB);

    float axl, axh, ayl, ayh, azl, azh;
    upk2(ax2, axl, axh);
    upk2(ay2, ayl, ayh);
    upk2(az2, azl, azh);

    atomicAdd(&out[3 * i + 0], axl + axh);
    atomicAdd(&out[3 * i + 1], ayl + ayh);
    atomicAdd(&out[3 * i + 2], azl + azh);
}

extern "C" void kernel_launch(void* const* d_in, const int* in_sizes, int n_in,
                              void* d_out, int out_size) {
    const float* rs  = (const float*)d_in[0];
    const float* sw1 = (const float*)d_in[1];
    const float* sb1 = (const float*)d_in[2];
    const float* swo = (const float*)d_in[3];
    const float* sbo = (const float*)d_in[4];
    const float* dw1 = (const float*)d_in[5];
    const float* db1 = (const float*)d_in[6];
    const float* dwo = (const float*)d_in[7];
    const float* dbo = (const float*)d_in[8];
    float* out = (float*)d_out;

    const int buildGrid = INIT_CTAS + (2 * TBL) / (BTHREADS / 32);
    build_and_init<<<buildGrid, BTHREADS>>>(rs, out,
                                            sw1, sb1, swo, sbo,
                                            dw1, db1, dwo, dbo);

    dim3 grid(N_TOT / THREADS, N_TOT / CHUNK);   // (16, 64) — single wave
    backflow_kernel<<<grid, THREADS>>>(rs, out);
}

// round 9
// speedup vs baseline: 1.0963x; 1.0963x over previous
#include <cuda_runtime.h>
#include <math.h>

#define N_TOT   4096
#define N_UP    2048
#define HIDDEN  32
#define BOX     10.0f
#define TBL     4096
#define SMAX    25.0f        // r_cut^2 = 5^2
#define CHUNK   64
#define THREADS 256          // main kernel CTA size (rows per CTA)
#define BTHREADS 256         // build kernel CTA size
#define INIT_CTAS 16

#define MAGIC     12582912.0f        // 1.5 * 2^23
#define BASEBITS  0x4B400000u        // float bits of MAGIC
#define CAPBITS   (BASEBITS + (TBL - 1))

typedef unsigned long long u64;

// ---- packed f32x2 helpers (sm_103a; ptxas never emits these from C++) ----
__device__ __forceinline__ u64 pk2(float lo, float hi) {
    u64 r; asm("mov.b64 %0,{%1,%2};" : "=l"(r) : "f"(lo), "f"(hi)); return r;
}
__device__ __forceinline__ void upk2u(u64 v, unsigned& lo, unsigned& hi) {
    asm("mov.b64 {%0,%1},%2;" : "=r"(lo), "=r"(hi) : "l"(v));
}
__device__ __forceinline__ void upk2(u64 v, float& lo, float& hi) {
    asm("mov.b64 {%0,%1},%2;" : "=f"(lo), "=f"(hi) : "l"(v));
}
__device__ __forceinline__ u64 add2(u64 a, u64 b) {
    u64 r; asm("add.rn.f32x2 %0,%1,%2;" : "=l"(r) : "l"(a), "l"(b)); return r;
}
__device__ __forceinline__ u64 fma2(u64 a, u64 b, u64 c) {
    u64 r; asm("fma.rn.f32x2 %0,%1,%2,%3;" : "=l"(r) : "l"(a), "l"(b), "l"(c)); return r;
}

// Precomputed f(s) tables (values pre-divided by coord scale cs).
// Nearest-neighbor lookup: plain float entries. [0]=same, [1]=diff.
__device__ __align__(16) float g_tab[2][TBL];

// ---------------------------------------------------------------------------
__device__ __forceinline__ float decay_of_s(float s) {
    float r  = sqrtf(s + 1e-15f);
    float xn = fminf(r * (1.0f / 5.0f), 1.0f - 1e-5f);
    float u  = 1.0f - xn * xn;
    return expf(1.0f - 1.0f / u);
}
__device__ __forceinline__ float unit_contrib(float decay, float w1, float b1, float wo) {
    float z = fmaf(decay, w1, b1);
    float h = z / (1.0f + expf(-z));
    return h * wo;
}

// Fused: build tables (warp per entry, lane per hidden unit) + out=rs init.
__global__ void __launch_bounds__(BTHREADS)
build_and_init(const float* __restrict__ rs, float* __restrict__ out,
               const float* __restrict__ sw1, const float* __restrict__ sb1,
               const float* __restrict__ swo, const float* __restrict__ sbo,
               const float* __restrict__ dw1, const float* __restrict__ db1,
               const float* __restrict__ dwo, const float* __restrict__ dbo) {
    const int bid = blockIdx.x;
    const int tid = threadIdx.x;

    if (bid < INIT_CTAS) {
        for (int i = bid * BTHREADS + tid; i < N_TOT * 3; i += INIT_CTAS * BTHREADS)
            out[i] = rs[i];
        return;
    }

    const int wglob = (bid - INIT_CTAS) * (BTHREADS / 32) + (tid >> 5);
    if (wglob >= 2 * TBL) return;
    const int net  = wglob / TBL;
    const int k    = wglob % TBL;
    const int lane = tid & 31;

    const float w1 = net ? dw1[lane] : sw1[lane];
    const float b1 = net ? db1[lane] : sb1[lane];
    const float wo = net ? dwo[lane] : swo[lane];
    const float bo = net ? dbo[0]    : sbo[0];

    const float h = SMAX / (float)(TBL - 1);
    const float d0 = decay_of_s((float)k * h);

    float a0 = unit_contrib(d0, w1, b1, wo);
    #pragma unroll
    for (int off = 16; off > 0; off >>= 1)
        a0 += __shfl_xor_sync(0xFFFFFFFFu, a0, off);
    if (lane == 0) {
        const float cs = sqrtf((float)(TBL - 1) / SMAX);   // coord scale
        g_tab[net][k] = (a0 + bo) * d0 / cs;
    }
}

// ---------------------------------------------------------------------------
// Main pairwise kernel: grid (16 x 64) = 1024 CTAs, 256 threads,
// min 7 CTAs/SM resident (87% occ). Coordinates pre-scaled so t = |d'|^2 is
// the table coordinate; nearest-entry lookup with magic bias folded into
// the r^2 reduction. Two j's per iteration via f32x2 packing.
// ---------------------------------------------------------------------------
__global__ void __launch_bounds__(THREADS, 7)
backflow_kernel(const float* __restrict__ rs, float* __restrict__ out) {
    __shared__ __align__(16) float s_tab[TBL];             // 16 KB
    // per j-pair: (x0,x1,y0,y1) as ulonglong2, (z0,z1) as u64
    __shared__ __align__(16) ulonglong2 sjxy[CHUNK / 2];
    __shared__ __align__(16) u64        sjz [CHUNK / 2];

    const int tid    = threadIdx.x;
    const int rowBlk = blockIdx.x;       // 0..15 (256 rows each)
    const int jBlk   = blockIdx.y;       // 0..63 (64 cols each)
    const int i      = rowBlk * THREADS + tid;
    const int j0     = jBlk * CHUNK;

    const int net = ((rowBlk < 8) == (jBlk < 32)) ? 0 : 1;

    const float cs   = sqrtf((float)(TBL - 1) / SMAX);   // coord scale
    const float BOXS = BOX * cs;

    // stage table (16 KB): 1024 float4 over 256 threads
    {
        const float4* src = (const float4*)g_tab[net];
        float4*       dst = (float4*)s_tab;
        #pragma unroll
        for (int t = tid; t < TBL / 4; t += THREADS) dst[t] = src[t];
    }
    if (tid < CHUNK) {
        int j = j0 + tid;
        int c = tid >> 1, l = tid & 1;
        float* fxy = (float*)sjxy;
        float* fz  = (float*)sjz;
        fxy[4 * c + l]     = -cs * rs[3 * j + 0];
        fxy[4 * c + 2 + l] = -cs * rs[3 * j + 1];
        fz [2 * c + l]     = -cs * rs[3 * j + 2];
    }
    __syncthreads();

    const float xi = cs * rs[3 * i + 0];
    const float yi = cs * rs[3 * i + 1];
    const float zi = cs * rs[3 * i + 2];
    const u64 xi2 = pk2(xi, xi);
    const u64 yi2 = pk2(yi, yi);
    const u64 zi2 = pk2(zi, zi);

    const u64 c_invb = pk2(1.0f / BOXS, 1.0f / BOXS);
    const u64 c_mag  = pk2(MAGIC, MAGIC);
    const u64 c_nmag = pk2(-MAGIC, -MAGIC);
    const u64 c_nb   = pk2(-BOXS, -BOXS);

    u64 ax2 = 0, ay2 = 0, az2 = 0;   // packed (0.0f, 0.0f)

    #pragma unroll 8
    for (int c = 0; c < CHUNK / 2; c++) {
        const ulonglong2 pj = sjxy[c];     // broadcast LDS.128
        const u64        zj = sjz [c];     // broadcast LDS.64

        u64 dx = add2(xi2, pj.x);
        u64 dy = add2(yi2, pj.y);
        u64 dz = add2(zi2, zj);

        // min image (scaled box): d -= BOXS * round(d/BOXS) via magic constant
        u64 mx = fma2(dx, c_invb, c_mag);
        u64 my = fma2(dy, c_invb, c_mag);
        u64 mz = fma2(dz, c_invb, c_mag);
        dx = fma2(add2(mx, c_nmag), c_nb, dx);
        dy = fma2(add2(my, c_nmag), c_nb, dy);
        dz = fma2(add2(mz, c_nmag), c_nb, dz);

        // t + MAGIC in one chain: nearest index bits fall out directly
        u64 m2 = fma2(dz, dz, fma2(dy, dy, fma2(dx, dx, c_mag)));

        unsigned kb0, kb1;
        upk2u(m2, kb0, kb1);
        kb0 = min(kb0, CAPBITS);
        kb1 = min(kb1, CAPBITS);

        float f0 = s_tab[kb0 - BASEBITS];
        float f1 = s_tab[kb1 - BASEBITS];

        const u64 f2 = pk2(f0, f1);
        ax2 = fma2(f2, dx, ax2);
        ay2 = fma2(f2, dy, ay2);
        az2 = fma2(f2, dz, az2);
    }

    float axl, axh, ayl, ayh, azl, azh;
    upk2(ax2, axl, axh);
    upk2(ay2, ayl, ayh);
    upk2(az2, azl, azh);

    atomicAdd(&out[3 * i + 0], axl + axh);
    atomicAdd(&out[3 * i + 1], ayl + ayh);
    atomicAdd(&out[3 * i + 2], azl + azh);
}

extern "C" void kernel_launch(void* const* d_in, const int* in_sizes, int n_in,
                              void* d_out, int out_size) {
    const float* rs  = (const float*)d_in[0];
    const float* sw1 = (const float*)d_in[1];
    const float* sb1 = (const float*)d_in[2];
    const float* swo = (const float*)d_in[3];
    const float* sbo = (const float*)d_in[4];
    const float* dw1 = (const float*)d_in[5];
    const float* db1 = (const float*)d_in[6];
    const float* dwo = (const float*)d_in[7];
    const float* dbo = (const float*)d_in[8];
    float* out = (float*)d_out;

    const int buildGrid = INIT_CTAS + (2 * TBL) / (BTHREADS / 32);
    build_and_init<<<buildGrid, BTHREADS>>>(rs, out,
                                            sw1, sb1, swo, sbo,
                                            dw1, db1, dwo, dbo);

    dim3 grid(N_TOT / THREADS, N_TOT / CHUNK);   // (16, 64) — single wave
    backflow_kernel<<<grid, THREADS>>>(rs, out);
}